// round 15
// baseline (speedup 1.0000x reference)
#include <cuda_runtime.h>
#include <cuda_fp16.h>
#include <cstdint>

// ---------------- problem constants ----------------
#define BB      10000
#define TED     512
#define GG      64
#define NN      2000
#define EE      64000
#define MDIM    15
#define NOISE_D 128
#define PAC     10
#define PROWS   1000          // B / PAC
#define PACDIM  6400          // (TED + NOISE) * PAC
#define D0      1024
#define D1      512

#define MR      1024
#define KINP    5120
#define KNOI    1280
#define KT1     PACDIM        // 6400
#define KT2     D0            // 1024
#define SPLITA  4
#define SPLITB  4
#define NSLICE  (SPLITA + SPLITB)   // 8
#define SPLIT2  8
#define GCN_SPL 8
#define EPC     (EE / GCN_SPL)

// ---------------- device scratch (static, allocation-free) ----------------
__device__ float d_deg [GG * NN];     // zero at load; gvec restores zero
__device__ float d_gout[GG * NN];     // zero at load; gvec restores zero
__device__ float d_gvecp[GG * 8 * NOISE_D];
__device__ __align__(16) __half d_a1 [(long)MR * KT1];
__device__ __align__(16) __half d_bt0[(long)D0 * KT1];
__device__ __align__(16) __half d_a2 [(long)MR * KT2];
__device__ __align__(16) __half d_b1t[(long)D1 * KT2];
__device__ __align__(16) float d_p1[(long)NSLICE * MR * D0];
__device__ __align__(16) float d_p2[(long)SPLIT2 * MR * D1];

// ---------------- side stream + events ----------------
struct SideStream {
    cudaStream_t s;
    cudaEvent_t e_fork, e_copy, e_w0, e_gA;
    SideStream() {
        cudaStreamCreateWithFlags(&s, cudaStreamNonBlocking);
        cudaEventCreateWithFlags(&e_fork, cudaEventDisableTiming);
        cudaEventCreateWithFlags(&e_copy, cudaEventDisableTiming);
        cudaEventCreateWithFlags(&e_w0, cudaEventDisableTiming);
        cudaEventCreateWithFlags(&e_gA, cudaEventDisableTiming);
    }
};
static SideStream g_side;

// ---------------- PTX helpers ----------------
__device__ __forceinline__ uint32_t smem_u32(const void* p) {
    return (uint32_t)__cvta_generic_to_shared(p);
}
#define SWZ(off) ((off) ^ (((off) >> 3) & 0x70))

__device__ __forceinline__ void cp16(uint32_t dst, const void* src) {
    asm volatile("cp.async.cg.shared.global [%0], [%1], 16;" :: "r"(dst), "l"(src) : "memory");
}
#define CP_COMMIT() asm volatile("cp.async.commit_group;" ::: "memory")
#define CP_WAIT(n)  asm volatile("cp.async.wait_group %0;" :: "n"(n) : "memory")

__device__ __forceinline__ void ldsm_x4(uint32_t* d, uint32_t addr) {
    asm volatile("ldmatrix.sync.aligned.m8n8.x4.shared.b16 {%0,%1,%2,%3}, [%4];"
                 : "=r"(d[0]), "=r"(d[1]), "=r"(d[2]), "=r"(d[3]) : "r"(addr));
}
__device__ __forceinline__ void mma16816(float* c, const uint32_t* a, uint32_t b0, uint32_t b1) {
    asm volatile("mma.sync.aligned.m16n8k16.row.col.f32.f16.f16.f32 "
                 "{%0,%1,%2,%3}, {%4,%5,%6,%7}, {%8,%9}, {%0,%1,%2,%3};"
                 : "+f"(c[0]), "+f"(c[1]), "+f"(c[2]), "+f"(c[3])
                 : "r"(a[0]), "r"(a[1]), "r"(a[2]), "r"(a[3]), "r"(b0), "r"(b1));
}

// ---------------- GCN pass 1: partial degree ----------------
__global__ void __launch_bounds__(512)
gcn_deg_kernel(const int* __restrict__ ei) {
    __shared__ float s_deg[NN];
    int g = blockIdx.x >> 3, q = blockIdx.x & 7;
    int t = threadIdx.x;
    float init = (q == 0) ? 1.0f : 0.0f;
    for (int i = t; i < NN; i += 512) s_deg[i] = init;
    __syncthreads();
    const int4* dst4 = reinterpret_cast<const int4*>(
        ei + (long)g * 2 * EE + EE + q * EPC);
    for (int e = t; e < EPC / 4; e += 512) {
        int4 d = dst4[e];
        atomicAdd(&s_deg[d.x], 1.0f);
        atomicAdd(&s_deg[d.y], 1.0f);
        atomicAdd(&s_deg[d.z], 1.0f);
        atomicAdd(&s_deg[d.w], 1.0f);
    }
    __syncthreads();
    for (int i = t; i < NN; i += 512)
        atomicAdd(&d_deg[g * NN + i], s_deg[i]);
}

// ---------------- GCN pass 2: messages (dinv inline) ----------------
__global__ void __launch_bounds__(512)
gcn_msg_kernel(const int* __restrict__ ei, const float* __restrict__ gx,
               const float* __restrict__ gw, const float* __restrict__ gb) {
    __shared__ float s_xs [NN];
    __shared__ float s_di [NN];
    __shared__ float s_out[NN];
    int g = blockIdx.x >> 3, q = blockIdx.x & 7;
    int t = threadIdx.x;
    float w = gw[0], b = gb[0];
    bool lead = (q == 0);
    for (int i = t; i < NN; i += 512) {
        float dv = rsqrtf(d_deg[g * NN + i]);
        float xs = gx[g * NN + i] * w * dv;
        s_di[i] = dv;
        s_xs[i] = xs;
        s_out[i] = lead ? (xs * dv + b) : 0.0f;
    }
    __syncthreads();
    const int4* src4 = reinterpret_cast<const int4*>(ei + (long)g * 2 * EE + q * EPC);
    const int4* dst4 = reinterpret_cast<const int4*>(ei + (long)g * 2 * EE + EE + q * EPC);
    for (int e = t; e < EPC / 4; e += 512) {
        int4 s = src4[e];
        int4 d = dst4[e];
        atomicAdd(&s_out[d.x], s_xs[s.x] * s_di[d.x]);
        atomicAdd(&s_out[d.y], s_xs[s.y] * s_di[d.y]);
        atomicAdd(&s_out[d.z], s_xs[s.z] * s_di[d.z]);
        atomicAdd(&s_out[d.w], s_xs[s.w] * s_di[d.w]);
    }
    __syncthreads();
    for (int i = t; i < NN; i += 512)
        atomicAdd(&d_gout[g * NN + i], s_out[i]);
}

// ---------------- gvec partials + state restore ----------------
__global__ void gvec_kernel(const float* __restrict__ gme_w) {
    int g = blockIdx.x, c = blockIdx.y, j = threadIdx.x;
    __shared__ float sh[128];
    float a0 = 0.f, a1 = 0.f, a2 = 0.f, a3 = 0.f;
    int nbeg = c * 250, nend = nbeg + 250;
    for (int n0 = nbeg; n0 < nend; n0 += 128) {
        int n = n0 + j;
        float v = 0.0f;
        if (n < nend) {
            v = d_gout[g * NN + n];
            d_gout[g * NN + n] = 0.0f;
            d_deg [g * NN + n] = 0.0f;
        }
        sh[j] = v;
        __syncthreads();
        int lim = min(128, nend - n0);
        int i = 0;
        for (; i + 3 < lim; i += 4) {
            a0 = fmaf(sh[i],     gme_w[(long)(n0 + i)     * NOISE_D + j], a0);
            a1 = fmaf(sh[i + 1], gme_w[(long)(n0 + i + 1) * NOISE_D + j], a1);
            a2 = fmaf(sh[i + 2], gme_w[(long)(n0 + i + 2) * NOISE_D + j], a2);
            a3 = fmaf(sh[i + 3], gme_w[(long)(n0 + i + 3) * NOISE_D + j], a3);
        }
        for (; i < lim; ++i)
            a0 = fmaf(sh[i], gme_w[(long)(n0 + i) * NOISE_D + j], a0);
        __syncthreads();
    }
    d_gvecp[(g * 8 + c) * NOISE_D + j] = (a0 + a1) + (a2 + a3);
}

// ---------------- noise: 8 rows/block ----------------
__global__ void __launch_bounds__(128)
noise_kernel(const float* __restrict__ chain,
             const float* __restrict__ metadata,
             const int*   __restrict__ gids,
             const float* __restrict__ meta_w,
             const float* __restrict__ meta_b,
             const float* __restrict__ gme_w,
             const float* __restrict__ gme_b) {
    __shared__ float s_gw[32][NOISE_D];
    __shared__ float me[8][32];
    __shared__ int   sg[8];
    int b0 = blockIdx.x * 8, t = threadIdx.x;

    for (int i = t; i < 32 * NOISE_D; i += 128)
        s_gw[i >> 7][i & 127] = gme_w[(long)(NN + (i >> 7)) * NOISE_D + (i & 127)];
    if (t < 8) sg[t] = gids[b0 + t];

    #pragma unroll
    for (int rr = 0; rr < 2; ++rr) {
        int r = rr * 4 + (t >> 5);
        int c = t & 31;
        int b = b0 + r;
        float acc = meta_b[c];
        acc = fmaf(chain[b], meta_w[c], acc);
        #pragma unroll
        for (int i = 0; i < MDIM; ++i)
            acc = fmaf(metadata[b * MDIM + i], meta_w[(i + 1) * 32 + c], acc);
        me[r][c] = fmaxf(acc, 0.0f);
    }
    __syncthreads();

    float gb = gme_b[t];
    #pragma unroll
    for (int r = 0; r < 8; ++r) {
        int b = b0 + r, g = sg[r];
        float s = gb;
        #pragma unroll
        for (int c = 0; c < 8; ++c)
            s += d_gvecp[(g * 8 + c) * NOISE_D + t];
        #pragma unroll
        for (int i = 0; i < 32; ++i)
            s = fmaf(me[r][i], s_gw[i][t], s);
        int p = b / PAC, u = b - p * PAC;
        int k = KINP + u * NOISE_D + t;
        d_a1[(long)p * KT1 + k] = __float2half_rn(s);
    }
}

// ---------------- input_ -> fp16 A (input K region) ----------------
__global__ void copy_input_kernel(const float* __restrict__ input_) {
    int idx = blockIdx.x * blockDim.x + threadIdx.x;
    if (idx >= BB * (TED / 8)) return;
    int b = idx >> 6, q8 = (idx & 63) * 8;
    const float4* src = reinterpret_cast<const float4*>(input_ + (long)b * TED + q8);
    float4 v0 = src[0], v1 = src[1];
    __half2 h0 = __floats2half2_rn(v0.x, v0.y);
    __half2 h1 = __floats2half2_rn(v0.z, v0.w);
    __half2 h2 = __floats2half2_rn(v1.x, v1.y);
    __half2 h3 = __floats2half2_rn(v1.z, v1.w);
    int p = b / PAC, u = b - p * PAC;
    int k = u * TED + q8;
    __half2* dst = reinterpret_cast<__half2*>(&d_a1[(long)p * KT1 + k]);
    dst[0] = h0; dst[1] = h1; dst[2] = h2; dst[3] = h3;
}

// ---------------- fused weight transpose + fp16 (both weights, one launch) ---
#define W0_BLKS ((KT1 / 32) * (D0 / 32))
__global__ void __launch_bounds__(256)
convW_both_kernel(const float* __restrict__ w0, __half* __restrict__ bt0,
                  const float* __restrict__ w1, __half* __restrict__ b1t) {
    __shared__ float s[32][33];
    bool first = blockIdx.x < W0_BLKS;
    int bid = first ? blockIdx.x : blockIdx.x - W0_BLKS;
    const float* w = first ? w0 : w1;
    __half* out    = first ? bt0 : b1t;
    const int K = first ? KT1 : KT2;
    const int N = first ? D0 : D1;
    int kb = first ? (KT1 / 32) : (KT2 / 32);
    int k0 = (bid % kb) * 32, n0 = (bid / kb) * 32;

    int tx = threadIdx.x & 31, ty = threadIdx.x >> 5;
    #pragma unroll
    for (int r = 0; r < 4; ++r)
        s[ty + r * 8][tx] = w[(long)(k0 + ty + r * 8) * N + n0 + tx];
    __syncthreads();
    #pragma unroll
    for (int r = 0; r < 4; ++r) {
        int n = n0 + ty + r * 8;
        int kk = k0 + tx;
        if (first) {
            int u = kk / 640, c = kk - u * 640;
            kk = (c < TED) ? (u * TED + c) : (KINP + u * NOISE_D + (c - TED));
        }
        out[(long)n * K + kk] = __float2half_rn(s[tx][ty + r * 8]);
    }
}

// ---------------- mma.sync fp16 GEMM: 128 thr, 4 warps 64x64, BK=64 ----------
template<int KTOT, int KSPLIT, int NTOT>
__global__ void __launch_bounds__(128, 2)
mma_gemm_kernel(const __half* __restrict__ A,
                const __half* __restrict__ Bt,
                float* __restrict__ Part, int kofs) {
    const int NITER = KSPLIT / 64;
    const int STG   = 32768;
    extern __shared__ __align__(1024) char sm[];
    uint32_t sb = smem_u32(sm);

    int tid = threadIdx.x;
    int lane = tid & 31;
    int wid  = tid >> 5;
    int wm   = wid & 1;
    int wn   = wid >> 1;
    int row0 = blockIdx.y * 128, col0 = blockIdx.x * 128;
    int kbase0 = kofs + blockIdx.z * KSPLIT;

    auto load_stage = [&](int stage, int kbase) {
        uint32_t aT = sb + stage * STG;
        uint32_t bT = aT + 16384;
        #pragma unroll
        for (int i = 0; i < 8; ++i) {
            int q = tid + 128 * i;
            int r = q >> 3, c = q & 7;
            cp16(aT + SWZ(r * 128 + c * 16),
                 A + (long)(row0 + r) * KTOT + kbase + c * 8);
        }
        #pragma unroll
        for (int i = 0; i < 8; ++i) {
            int q = tid + 128 * i;
            int r = q >> 3, c = q & 7;
            cp16(bT + SWZ(r * 128 + c * 16),
                 Bt + (long)(col0 + r) * KTOT + kbase + c * 8);
        }
    };

    float acc[4][8][4];
    #pragma unroll
    for (int mf = 0; mf < 4; ++mf)
        #pragma unroll
        for (int nf = 0; nf < 8; ++nf)
            #pragma unroll
            for (int j = 0; j < 4; ++j) acc[mf][nf][j] = 0.0f;

    load_stage(0, kbase0); CP_COMMIT();
    load_stage(1, kbase0 + 64); CP_COMMIT();

    int a_row = wm * 64 + (lane & 15);
    int a_kb  = (lane >> 4) << 4;
    int b_row = wn * 64 + (lane & 7) + ((lane >> 4) & 1) * 8;
    int b_kb  = ((lane >> 3) & 1) << 4;

    for (int it = 0; it < NITER; ++it) {
        CP_WAIT(1);
        __syncthreads();
        if (it + 2 < NITER) load_stage((it + 2) % 3, kbase0 + (it + 2) * 64);
        CP_COMMIT();

        uint32_t aT = sb + (it % 3) * STG;
        uint32_t bT = aT + 16384;

        #pragma unroll
        for (int kk = 0; kk < 4; ++kk) {
            uint32_t a[4][4];
            #pragma unroll
            for (int mf = 0; mf < 4; ++mf)
                ldsm_x4(a[mf], aT + SWZ((a_row + mf * 16) * 128 + kk * 32 + a_kb));
            uint32_t b[4][4];
            #pragma unroll
            for (int nfp = 0; nfp < 4; ++nfp)
                ldsm_x4(b[nfp], bT + SWZ((b_row + nfp * 16) * 128 + kk * 32 + b_kb));
            #pragma unroll
            for (int mf = 0; mf < 4; ++mf)
                #pragma unroll
                for (int nfp = 0; nfp < 4; ++nfp) {
                    mma16816(acc[mf][2 * nfp],     a[mf], b[nfp][0], b[nfp][1]);
                    mma16816(acc[mf][2 * nfp + 1], a[mf], b[nfp][2], b[nfp][3]);
                }
        }
    }

    float* P = Part + (long)blockIdx.z * MR * NTOT;
    #pragma unroll
    for (int mf = 0; mf < 4; ++mf) {
        int gr = row0 + wm * 64 + mf * 16 + (lane >> 2);
        #pragma unroll
        for (int nf = 0; nf < 8; ++nf) {
            int gc = col0 + wn * 64 + nf * 8 + (lane & 3) * 2;
            *reinterpret_cast<float2*>(&P[(long)gr * NTOT + gc]) =
                make_float2(acc[mf][nf][0], acc[mf][nf][1]);
            *reinterpret_cast<float2*>(&P[(long)(gr + 8) * NTOT + gc]) =
                make_float2(acc[mf][nf][2], acc[mf][nf][3]);
        }
    }
}

// reduce gemm1: sum NSLICE slices + bias + lrelu -> fp16 A2
__global__ void reduce1_kernel(const float* __restrict__ bias) {
    long i = (long)blockIdx.x * blockDim.x + threadIdx.x;
    if (i >= (long)PROWS * D0) return;
    int m = (int)(i >> 10), n = (int)(i & 1023);
    float v = 0.0f;
    #pragma unroll
    for (int s = 0; s < NSLICE; ++s)
        v += d_p1[(long)s * MR * D0 + (long)m * D0 + n];
    v += bias[n];
    v = (v >= 0.f) ? v : 0.2f * v;
    d_a2[(long)m * KT2 + n] = __float2half_rn(v);
}

// fused: reduce gemm2 slices + bias + lrelu + dot(w2) + b2 -> out
__global__ void __launch_bounds__(512)
final2_kernel(const float* __restrict__ b1,
              const float* __restrict__ w2,
              const float* __restrict__ b2,
              float* __restrict__ out) {
    int m = blockIdx.x, t = threadIdx.x;
    float v = 0.0f;
    #pragma unroll
    for (int s = 0; s < SPLIT2; ++s)
        v += d_p2[(long)s * MR * D1 + (long)m * D1 + t];
    v += b1[t];
    v = (v >= 0.f) ? v : 0.2f * v;
    float s = v * w2[t];
    #pragma unroll
    for (int off = 16; off > 0; off >>= 1)
        s += __shfl_down_sync(0xffffffff, s, off);
    __shared__ float ws[16];
    if ((t & 31) == 0) ws[t >> 5] = s;
    __syncthreads();
    if (t < 32) {
        float r = (t < 16) ? ws[t] : 0.0f;
        #pragma unroll
        for (int off = 8; off > 0; off >>= 1)
            r += __shfl_down_sync(0xffffffff, r, off);
        if (t == 0) out[m] = r + b2[0];
    }
}

// ---------------- launch ----------------
extern "C" void kernel_launch(void* const* d_in, const int* in_sizes, int n_in,
                              void* d_out, int out_size) {
    const float* input_   = (const float*)d_in[0];
    const float* graphs_x = (const float*)d_in[1];
    const int*   edge_idx = (const int*)  d_in[2];
    const int*   graph_id = (const int*)  d_in[3];
    const float* chain    = (const float*)d_in[4];
    const float* metadata = (const float*)d_in[5];
    const float* gcn_w    = (const float*)d_in[6];
    const float* gcn_b    = (const float*)d_in[7];
    const float* meta_w   = (const float*)d_in[8];
    const float* meta_b   = (const float*)d_in[9];
    const float* gme_w    = (const float*)d_in[10];
    const float* gme_b    = (const float*)d_in[11];
    const float* seq_w0   = (const float*)d_in[12];
    const float* seq_b0   = (const float*)d_in[13];
    const float* seq_w1   = (const float*)d_in[14];
    const float* seq_b1   = (const float*)d_in[15];
    const float* seq_w2   = (const float*)d_in[16];
    const float* seq_b2   = (const float*)d_in[17];
    float* out = (float*)d_out;

    const int DSMEM = 3 * 32768;   // 96 KB
    cudaFuncSetAttribute((const void*)mma_gemm_kernel<KT1, KINP / SPLITA, D0>,
                         cudaFuncAttributeMaxDynamicSharedMemorySize, DSMEM);
    cudaFuncSetAttribute((const void*)mma_gemm_kernel<KT1, KNOI / SPLITB, D0>,
                         cudaFuncAttributeMaxDynamicSharedMemorySize, DSMEM);
    cudaFuncSetAttribute((const void*)mma_gemm_kernel<KT2, KT2 / SPLIT2, D1>,
                         cudaFuncAttributeMaxDynamicSharedMemorySize, DSMEM);

    __half *a1, *bt0, *a2, *b1t;
    float *p1, *p2;
    cudaGetSymbolAddress((void**)&a1,  d_a1);
    cudaGetSymbolAddress((void**)&bt0, d_bt0);
    cudaGetSymbolAddress((void**)&a2,  d_a2);
    cudaGetSymbolAddress((void**)&b1t, d_b1t);
    cudaGetSymbolAddress((void**)&p1,  d_p1);
    cudaGetSymbolAddress((void**)&p2,  d_p2);

    // ---- fork ----
    cudaEventRecord(g_side.e_fork, 0);
    cudaStreamWaitEvent(g_side.s, g_side.e_fork, 0);

    // main stream head: copy_input (independent of GCN; feeds gemmA)
    copy_input_kernel<<<(BB * (TED / 8) + 255) / 256, 256>>>(input_);
    cudaEventRecord(g_side.e_copy, 0);

    // side stream: convW(both) -> [wait copy] -> gemmA (input-K region)
    convW_both_kernel<<<W0_BLKS + (KT2 / 32) * (D1 / 32), 256, 0, g_side.s>>>(
        seq_w0, bt0, seq_w1, b1t);
    cudaEventRecord(g_side.e_w0, g_side.s);
    cudaStreamWaitEvent(g_side.s, g_side.e_copy, 0);
    {
        dim3 gA(D0 / 128, MR / 128, SPLITA);
        mma_gemm_kernel<KT1, KINP / SPLITA, D0>
            <<<gA, 128, DSMEM, g_side.s>>>(a1, bt0, p1, 0);
    }
    cudaEventRecord(g_side.e_gA, g_side.s);

    // main stream: GCN (deg -> msg) -> gvec (restores state) -> noise
    gcn_deg_kernel<<<GG * GCN_SPL, 512>>>(edge_idx);
    gcn_msg_kernel<<<GG * GCN_SPL, 512>>>(edge_idx, graphs_x, gcn_w, gcn_b);
    gvec_kernel<<<dim3(GG, 8), 128>>>(gme_w);
    noise_kernel<<<BB / 8, 128>>>(chain, metadata, graph_id, meta_w, meta_b, gme_w, gme_b);

    // gemmB (noise-K region): slices 4..7
    cudaStreamWaitEvent(0, g_side.e_w0, 0);
    {
        dim3 gB(D0 / 128, MR / 128, SPLITB);
        mma_gemm_kernel<KT1, KNOI / SPLITB, D0>
            <<<gB, 128, DSMEM>>>(a1, bt0, p1 + (long)SPLITA * MR * D0, KINP);
    }

    // join gemmA, reduce, gemm2, fused final
    cudaStreamWaitEvent(0, g_side.e_gA, 0);
    reduce1_kernel<<<(PROWS * D0 + 255) / 256, 256>>>(seq_b0);

    {
        dim3 g2(D1 / 128, MR / 128, SPLIT2);
        mma_gemm_kernel<KT2, KT2 / SPLIT2, D1>
            <<<g2, 128, DSMEM>>>(a2, b1t, p2, 0);
    }
    final2_kernel<<<PROWS, 512>>>(seq_b1, seq_w2, seq_b2, out);
}

// round 16
// speedup vs baseline: 1.0961x; 1.0961x over previous
#include <cuda_runtime.h>
#include <cuda_fp16.h>
#include <cstdint>

// ---------------- problem constants ----------------
#define BB      10000
#define TED     512
#define GG      64
#define NN      2000
#define EE      64000
#define MDIM    15
#define NOISE_D 128
#define PAC     10
#define PROWS   1000          // B / PAC
#define PACDIM  6400          // (TED + NOISE) * PAC
#define D0      1024
#define D1      512

#define MR      1024
#define KINP    5120
#define KNOI    1280
#define KT1     PACDIM        // 6400
#define KT2     D0            // 1024
#define SPLITA  4
#define SPLITB  4
#define NSLICE  (SPLITA + SPLITB)   // 8
#define SPLIT2  4
#define GCN_SPL 8
#define EPC     (EE / GCN_SPL)

// ---------------- device scratch (static, allocation-free) ----------------
__device__ float d_deg [GG * NN];     // zero at load; gvec restores zero
__device__ float d_gout[GG * NN];     // zero at load; gvec restores zero
__device__ float d_gvecp[GG * 8 * NOISE_D];
__device__ __align__(16) __half d_a1 [(long)MR * KT1];
__device__ __align__(16) __half d_bt0[(long)D0 * KT1];
__device__ __align__(16) __half d_a2 [(long)MR * KT2];
__device__ __align__(16) __half d_b1t[(long)D1 * KT2];
__device__ __align__(16) float d_p1[(long)NSLICE * MR * D0];
__device__ __align__(16) float d_p2[(long)SPLIT2 * MR * D1];

// ---------------- side stream + events ----------------
struct SideStream {
    cudaStream_t s;
    cudaEvent_t e_fork, e_w0, e_r1a;
    SideStream() {
        cudaStreamCreateWithFlags(&s, cudaStreamNonBlocking);
        cudaEventCreateWithFlags(&e_fork, cudaEventDisableTiming);
        cudaEventCreateWithFlags(&e_w0, cudaEventDisableTiming);
        cudaEventCreateWithFlags(&e_r1a, cudaEventDisableTiming);
    }
};
static SideStream g_side;

// ---------------- PTX helpers ----------------
__device__ __forceinline__ uint32_t smem_u32(const void* p) {
    return (uint32_t)__cvta_generic_to_shared(p);
}
#define SWZ(off) ((off) ^ (((off) >> 3) & 0x70))

__device__ __forceinline__ void cp16(uint32_t dst, const void* src) {
    asm volatile("cp.async.cg.shared.global [%0], [%1], 16;" :: "r"(dst), "l"(src) : "memory");
}
#define CP_COMMIT() asm volatile("cp.async.commit_group;" ::: "memory")
#define CP_WAIT(n)  asm volatile("cp.async.wait_group %0;" :: "n"(n) : "memory")

__device__ __forceinline__ void ldsm_x4(uint32_t* d, uint32_t addr) {
    asm volatile("ldmatrix.sync.aligned.m8n8.x4.shared.b16 {%0,%1,%2,%3}, [%4];"
                 : "=r"(d[0]), "=r"(d[1]), "=r"(d[2]), "=r"(d[3]) : "r"(addr));
}
__device__ __forceinline__ void mma16816(float* c, const uint32_t* a, uint32_t b0, uint32_t b1) {
    asm volatile("mma.sync.aligned.m16n8k16.row.col.f32.f16.f16.f32 "
                 "{%0,%1,%2,%3}, {%4,%5,%6,%7}, {%8,%9}, {%0,%1,%2,%3};"
                 : "+f"(c[0]), "+f"(c[1]), "+f"(c[2]), "+f"(c[3])
                 : "r"(a[0]), "r"(a[1]), "r"(a[2]), "r"(a[3]), "r"(b0), "r"(b1));
}

// ---------------- GCN pass 1: partial degree ----------------
__global__ void __launch_bounds__(512)
gcn_deg_kernel(const int* __restrict__ ei) {
    __shared__ float s_deg[NN];
    int g = blockIdx.x >> 3, q = blockIdx.x & 7;
    int t = threadIdx.x;
    float init = (q == 0) ? 1.0f : 0.0f;
    for (int i = t; i < NN; i += 512) s_deg[i] = init;
    __syncthreads();
    const int4* dst4 = reinterpret_cast<const int4*>(
        ei + (long)g * 2 * EE + EE + q * EPC);
    for (int e = t; e < EPC / 4; e += 512) {
        int4 d = dst4[e];
        atomicAdd(&s_deg[d.x], 1.0f);
        atomicAdd(&s_deg[d.y], 1.0f);
        atomicAdd(&s_deg[d.z], 1.0f);
        atomicAdd(&s_deg[d.w], 1.0f);
    }
    __syncthreads();
    for (int i = t; i < NN; i += 512)
        atomicAdd(&d_deg[g * NN + i], s_deg[i]);
}

// ---------------- GCN pass 2: messages (dinv inline) ----------------
__global__ void __launch_bounds__(512)
gcn_msg_kernel(const int* __restrict__ ei, const float* __restrict__ gx,
               const float* __restrict__ gw, const float* __restrict__ gb) {
    __shared__ float s_xs [NN];
    __shared__ float s_di [NN];
    __shared__ float s_out[NN];
    int g = blockIdx.x >> 3, q = blockIdx.x & 7;
    int t = threadIdx.x;
    float w = gw[0], b = gb[0];
    bool lead = (q == 0);
    for (int i = t; i < NN; i += 512) {
        float dv = rsqrtf(d_deg[g * NN + i]);
        float xs = gx[g * NN + i] * w * dv;
        s_di[i] = dv;
        s_xs[i] = xs;
        s_out[i] = lead ? (xs * dv + b) : 0.0f;
    }
    __syncthreads();
    const int4* src4 = reinterpret_cast<const int4*>(ei + (long)g * 2 * EE + q * EPC);
    const int4* dst4 = reinterpret_cast<const int4*>(ei + (long)g * 2 * EE + EE + q * EPC);
    for (int e = t; e < EPC / 4; e += 512) {
        int4 s = src4[e];
        int4 d = dst4[e];
        atomicAdd(&s_out[d.x], s_xs[s.x] * s_di[d.x]);
        atomicAdd(&s_out[d.y], s_xs[s.y] * s_di[d.y]);
        atomicAdd(&s_out[d.z], s_xs[s.z] * s_di[d.z]);
        atomicAdd(&s_out[d.w], s_xs[s.w] * s_di[d.w]);
    }
    __syncthreads();
    for (int i = t; i < NN; i += 512)
        atomicAdd(&d_gout[g * NN + i], s_out[i]);
}

// ---------------- gvec partials + state restore ----------------
__global__ void gvec_kernel(const float* __restrict__ gme_w) {
    int g = blockIdx.x, c = blockIdx.y, j = threadIdx.x;
    __shared__ float sh[128];
    float a0 = 0.f, a1 = 0.f, a2 = 0.f, a3 = 0.f;
    int nbeg = c * 250, nend = nbeg + 250;
    for (int n0 = nbeg; n0 < nend; n0 += 128) {
        int n = n0 + j;
        float v = 0.0f;
        if (n < nend) {
            v = d_gout[g * NN + n];
            d_gout[g * NN + n] = 0.0f;
            d_deg [g * NN + n] = 0.0f;
        }
        sh[j] = v;
        __syncthreads();
        int lim = min(128, nend - n0);
        int i = 0;
        for (; i + 3 < lim; i += 4) {
            a0 = fmaf(sh[i],     gme_w[(long)(n0 + i)     * NOISE_D + j], a0);
            a1 = fmaf(sh[i + 1], gme_w[(long)(n0 + i + 1) * NOISE_D + j], a1);
            a2 = fmaf(sh[i + 2], gme_w[(long)(n0 + i + 2) * NOISE_D + j], a2);
            a3 = fmaf(sh[i + 3], gme_w[(long)(n0 + i + 3) * NOISE_D + j], a3);
        }
        for (; i < lim; ++i)
            a0 = fmaf(sh[i], gme_w[(long)(n0 + i) * NOISE_D + j], a0);
        __syncthreads();
    }
    d_gvecp[(g * 8 + c) * NOISE_D + j] = (a0 + a1) + (a2 + a3);
}

// ---------------- noise: 8 rows/block ----------------
__global__ void __launch_bounds__(128)
noise_kernel(const float* __restrict__ chain,
             const float* __restrict__ metadata,
             const int*   __restrict__ gids,
             const float* __restrict__ meta_w,
             const float* __restrict__ meta_b,
             const float* __restrict__ gme_w,
             const float* __restrict__ gme_b) {
    __shared__ float s_gw[32][NOISE_D];
    __shared__ float me[8][32];
    __shared__ int   sg[8];
    int b0 = blockIdx.x * 8, t = threadIdx.x;

    for (int i = t; i < 32 * NOISE_D; i += 128)
        s_gw[i >> 7][i & 127] = gme_w[(long)(NN + (i >> 7)) * NOISE_D + (i & 127)];
    if (t < 8) sg[t] = gids[b0 + t];

    #pragma unroll
    for (int rr = 0; rr < 2; ++rr) {
        int r = rr * 4 + (t >> 5);
        int c = t & 31;
        int b = b0 + r;
        float acc = meta_b[c];
        acc = fmaf(chain[b], meta_w[c], acc);
        #pragma unroll
        for (int i = 0; i < MDIM; ++i)
            acc = fmaf(metadata[b * MDIM + i], meta_w[(i + 1) * 32 + c], acc);
        me[r][c] = fmaxf(acc, 0.0f);
    }
    __syncthreads();

    float gb = gme_b[t];
    #pragma unroll
    for (int r = 0; r < 8; ++r) {
        int b = b0 + r, g = sg[r];
        float s = gb;
        #pragma unroll
        for (int c = 0; c < 8; ++c)
            s += d_gvecp[(g * 8 + c) * NOISE_D + t];
        #pragma unroll
        for (int i = 0; i < 32; ++i)
            s = fmaf(me[r][i], s_gw[i][t], s);
        int p = b / PAC, u = b - p * PAC;
        int k = KINP + u * NOISE_D + t;
        d_a1[(long)p * KT1 + k] = __float2half_rn(s);
    }
}

// ---------------- input_ -> fp16 A (input K region) ----------------
__global__ void copy_input_kernel(const float* __restrict__ input_) {
    int idx = blockIdx.x * blockDim.x + threadIdx.x;
    if (idx >= BB * (TED / 8)) return;
    int b = idx >> 6, q8 = (idx & 63) * 8;
    const float4* src = reinterpret_cast<const float4*>(input_ + (long)b * TED + q8);
    float4 v0 = src[0], v1 = src[1];
    __half2 h0 = __floats2half2_rn(v0.x, v0.y);
    __half2 h1 = __floats2half2_rn(v0.z, v0.w);
    __half2 h2 = __floats2half2_rn(v1.x, v1.y);
    __half2 h3 = __floats2half2_rn(v1.z, v1.w);
    int p = b / PAC, u = b - p * PAC;
    int k = u * TED + q8;
    __half2* dst = reinterpret_cast<__half2*>(&d_a1[(long)p * KT1 + k]);
    dst[0] = h0; dst[1] = h1; dst[2] = h2; dst[3] = h3;
}

// ---------------- fused weight transpose + fp16 (both weights, one launch) ---
#define W0_BLKS ((KT1 / 32) * (D0 / 32))
__global__ void __launch_bounds__(256)
convW_both_kernel(const float* __restrict__ w0, __half* __restrict__ bt0,
                  const float* __restrict__ w1, __half* __restrict__ b1t) {
    __shared__ float s[32][33];
    bool first = blockIdx.x < W0_BLKS;
    int bid = first ? blockIdx.x : blockIdx.x - W0_BLKS;
    const float* w = first ? w0 : w1;
    __half* out    = first ? bt0 : b1t;
    const int K = first ? KT1 : KT2;
    const int N = first ? D0 : D1;
    int kb = first ? (KT1 / 32) : (KT2 / 32);
    int k0 = (bid % kb) * 32, n0 = (bid / kb) * 32;

    int tx = threadIdx.x & 31, ty = threadIdx.x >> 5;
    #pragma unroll
    for (int r = 0; r < 4; ++r)
        s[ty + r * 8][tx] = w[(long)(k0 + ty + r * 8) * N + n0 + tx];
    __syncthreads();
    #pragma unroll
    for (int r = 0; r < 4; ++r) {
        int n = n0 + ty + r * 8;
        int kk = k0 + tx;
        if (first) {
            int u = kk / 640, c = kk - u * 640;
            kk = (c < TED) ? (u * TED + c) : (KINP + u * NOISE_D + (c - TED));
        }
        out[(long)n * K + kk] = __float2half_rn(s[tx][ty + r * 8]);
    }
}

// ---------------- mma.sync fp16 GEMM: 128 thr, 4 warps 64x64, BK=64 ----------
template<int KTOT, int KSPLIT, int NTOT>
__global__ void __launch_bounds__(128, 2)
mma_gemm_kernel(const __half* __restrict__ A,
                const __half* __restrict__ Bt,
                float* __restrict__ Part, int kofs) {
    const int NITER = KSPLIT / 64;
    const int STG   = 32768;
    extern __shared__ __align__(1024) char sm[];
    uint32_t sb = smem_u32(sm);

    int tid = threadIdx.x;
    int lane = tid & 31;
    int wid  = tid >> 5;
    int wm   = wid & 1;
    int wn   = wid >> 1;
    int row0 = blockIdx.y * 128, col0 = blockIdx.x * 128;
    int kbase0 = kofs + blockIdx.z * KSPLIT;

    auto load_stage = [&](int stage, int kbase) {
        uint32_t aT = sb + stage * STG;
        uint32_t bT = aT + 16384;
        #pragma unroll
        for (int i = 0; i < 8; ++i) {
            int q = tid + 128 * i;
            int r = q >> 3, c = q & 7;
            cp16(aT + SWZ(r * 128 + c * 16),
                 A + (long)(row0 + r) * KTOT + kbase + c * 8);
        }
        #pragma unroll
        for (int i = 0; i < 8; ++i) {
            int q = tid + 128 * i;
            int r = q >> 3, c = q & 7;
            cp16(bT + SWZ(r * 128 + c * 16),
                 Bt + (long)(col0 + r) * KTOT + kbase + c * 8);
        }
    };

    float acc[4][8][4];
    #pragma unroll
    for (int mf = 0; mf < 4; ++mf)
        #pragma unroll
        for (int nf = 0; nf < 8; ++nf)
            #pragma unroll
            for (int j = 0; j < 4; ++j) acc[mf][nf][j] = 0.0f;

    load_stage(0, kbase0); CP_COMMIT();
    load_stage(1, kbase0 + 64); CP_COMMIT();

    int a_row = wm * 64 + (lane & 15);
    int a_kb  = (lane >> 4) << 4;
    int b_row = wn * 64 + (lane & 7) + ((lane >> 4) & 1) * 8;
    int b_kb  = ((lane >> 3) & 1) << 4;

    for (int it = 0; it < NITER; ++it) {
        CP_WAIT(1);
        __syncthreads();
        if (it + 2 < NITER) load_stage((it + 2) % 3, kbase0 + (it + 2) * 64);
        CP_COMMIT();

        uint32_t aT = sb + (it % 3) * STG;
        uint32_t bT = aT + 16384;

        #pragma unroll
        for (int kk = 0; kk < 4; ++kk) {
            uint32_t a[4][4];
            #pragma unroll
            for (int mf = 0; mf < 4; ++mf)
                ldsm_x4(a[mf], aT + SWZ((a_row + mf * 16) * 128 + kk * 32 + a_kb));
            uint32_t b[4][4];
            #pragma unroll
            for (int nfp = 0; nfp < 4; ++nfp)
                ldsm_x4(b[nfp], bT + SWZ((b_row + nfp * 16) * 128 + kk * 32 + b_kb));
            #pragma unroll
            for (int mf = 0; mf < 4; ++mf)
                #pragma unroll
                for (int nfp = 0; nfp < 4; ++nfp) {
                    mma16816(acc[mf][2 * nfp],     a[mf], b[nfp][0], b[nfp][1]);
                    mma16816(acc[mf][2 * nfp + 1], a[mf], b[nfp][2], b[nfp][3]);
                }
        }
    }

    float* P = Part + (long)blockIdx.z * MR * NTOT;
    #pragma unroll
    for (int mf = 0; mf < 4; ++mf) {
        int gr = row0 + wm * 64 + mf * 16 + (lane >> 2);
        #pragma unroll
        for (int nf = 0; nf < 8; ++nf) {
            int gc = col0 + wn * 64 + nf * 8 + (lane & 3) * 2;
            *reinterpret_cast<float2*>(&P[(long)gr * NTOT + gc]) =
                make_float2(acc[mf][nf][0], acc[mf][nf][1]);
            *reinterpret_cast<float2*>(&P[(long)(gr + 8) * NTOT + gc]) =
                make_float2(acc[mf][nf][2], acc[mf][nf][3]);
        }
    }
}

// reduce1a: pre-sum gemmA slices 0..3 into slice 0 (runs concurrent w/ gemmB)
__global__ void reduce1a_kernel() {
    long i = (long)blockIdx.x * blockDim.x + threadIdx.x;
    if (i >= (long)PROWS * D0) return;
    int m = (int)(i >> 10), n = (int)(i & 1023);
    long o = (long)m * D0 + n;
    float v = d_p1[o];
    #pragma unroll
    for (int s = 1; s < SPLITA; ++s)
        v += d_p1[(long)s * MR * D0 + o];
    d_p1[o] = v;
}

// reduce1b: slice0 + gemmB slices + bias + lrelu -> fp16 A2
__global__ void reduce1b_kernel(const float* __restrict__ bias) {
    long i = (long)blockIdx.x * blockDim.x + threadIdx.x;
    if (i >= (long)PROWS * D0) return;
    int m = (int)(i >> 10), n = (int)(i & 1023);
    long o = (long)m * D0 + n;
    float v = d_p1[o];
    #pragma unroll
    for (int s = SPLITA; s < NSLICE; ++s)
        v += d_p1[(long)s * MR * D0 + o];
    v += bias[n];
    v = (v >= 0.f) ? v : 0.2f * v;
    d_a2[(long)m * KT2 + n] = __float2half_rn(v);
}

// fused: reduce gemm2 slices + bias + lrelu + dot(w2) + b2 -> out
__global__ void __launch_bounds__(512)
final2_kernel(const float* __restrict__ b1,
              const float* __restrict__ w2,
              const float* __restrict__ b2,
              float* __restrict__ out) {
    int m = blockIdx.x, t = threadIdx.x;
    float v = 0.0f;
    #pragma unroll
    for (int s = 0; s < SPLIT2; ++s)
        v += d_p2[(long)s * MR * D1 + (long)m * D1 + t];
    v += b1[t];
    v = (v >= 0.f) ? v : 0.2f * v;
    float s = v * w2[t];
    #pragma unroll
    for (int off = 16; off > 0; off >>= 1)
        s += __shfl_down_sync(0xffffffff, s, off);
    __shared__ float ws[16];
    if ((t & 31) == 0) ws[t >> 5] = s;
    __syncthreads();
    if (t < 32) {
        float r = (t < 16) ? ws[t] : 0.0f;
        #pragma unroll
        for (int off = 8; off > 0; off >>= 1)
            r += __shfl_down_sync(0xffffffff, r, off);
        if (t == 0) out[m] = r + b2[0];
    }
}

// ---------------- launch ----------------
extern "C" void kernel_launch(void* const* d_in, const int* in_sizes, int n_in,
                              void* d_out, int out_size) {
    const float* input_   = (const float*)d_in[0];
    const float* graphs_x = (const float*)d_in[1];
    const int*   edge_idx = (const int*)  d_in[2];
    const int*   graph_id = (const int*)  d_in[3];
    const float* chain    = (const float*)d_in[4];
    const float* metadata = (const float*)d_in[5];
    const float* gcn_w    = (const float*)d_in[6];
    const float* gcn_b    = (const float*)d_in[7];
    const float* meta_w   = (const float*)d_in[8];
    const float* meta_b   = (const float*)d_in[9];
    const float* gme_w    = (const float*)d_in[10];
    const float* gme_b    = (const float*)d_in[11];
    const float* seq_w0   = (const float*)d_in[12];
    const float* seq_b0   = (const float*)d_in[13];
    const float* seq_w1   = (const float*)d_in[14];
    const float* seq_b1   = (const float*)d_in[15];
    const float* seq_w2   = (const float*)d_in[16];
    const float* seq_b2   = (const float*)d_in[17];
    float* out = (float*)d_out;

    const int DSMEM = 3 * 32768;   // 96 KB
    cudaFuncSetAttribute((const void*)mma_gemm_kernel<KT1, KINP / SPLITA, D0>,
                         cudaFuncAttributeMaxDynamicSharedMemorySize, DSMEM);
    cudaFuncSetAttribute((const void*)mma_gemm_kernel<KT1, KNOI / SPLITB, D0>,
                         cudaFuncAttributeMaxDynamicSharedMemorySize, DSMEM);
    cudaFuncSetAttribute((const void*)mma_gemm_kernel<KT2, KT2 / SPLIT2, D1>,
                         cudaFuncAttributeMaxDynamicSharedMemorySize, DSMEM);

    __half *a1, *bt0, *a2, *b1t;
    float *p1, *p2;
    cudaGetSymbolAddress((void**)&a1,  d_a1);
    cudaGetSymbolAddress((void**)&bt0, d_bt0);
    cudaGetSymbolAddress((void**)&a2,  d_a2);
    cudaGetSymbolAddress((void**)&b1t, d_b1t);
    cudaGetSymbolAddress((void**)&p1,  d_p1);
    cudaGetSymbolAddress((void**)&p2,  d_p2);

    // ---- fork ----
    cudaEventRecord(g_side.e_fork, 0);
    cudaStreamWaitEvent(g_side.s, g_side.e_fork, 0);

    // side stream: convW(both) -> copy_input -> gemmA -> reduce1a (slices 0..3)
    convW_both_kernel<<<W0_BLKS + (KT2 / 32) * (D1 / 32), 256, 0, g_side.s>>>(
        seq_w0, bt0, seq_w1, b1t);
    cudaEventRecord(g_side.e_w0, g_side.s);
    copy_input_kernel<<<(BB * (TED / 8) + 255) / 256, 256, 0, g_side.s>>>(input_);
    {
        dim3 gA(D0 / 128, MR / 128, SPLITA);
        mma_gemm_kernel<KT1, KINP / SPLITA, D0>
            <<<gA, 128, DSMEM, g_side.s>>>(a1, bt0, p1, 0);
    }
    reduce1a_kernel<<<(PROWS * D0 + 255) / 256, 256, 0, g_side.s>>>();
    cudaEventRecord(g_side.e_r1a, g_side.s);

    // main stream: GCN (deg -> msg) -> gvec (restores state) -> noise
    gcn_deg_kernel<<<GG * GCN_SPL, 512>>>(edge_idx);
    gcn_msg_kernel<<<GG * GCN_SPL, 512>>>(edge_idx, graphs_x, gcn_w, gcn_b);
    gvec_kernel<<<dim3(GG, 8), 128>>>(gme_w);
    noise_kernel<<<BB / 8, 128>>>(chain, metadata, graph_id, meta_w, meta_b, gme_w, gme_b);

    // gemmB (noise-K region): slices 4..7 (concurrent with reduce1a on side)
    cudaStreamWaitEvent(0, g_side.e_w0, 0);
    {
        dim3 gB(D0 / 128, MR / 128, SPLITB);
        mma_gemm_kernel<KT1, KNOI / SPLITB, D0>
            <<<gB, 128, DSMEM>>>(a1, bt0, p1 + (long)SPLITA * MR * D0, KINP);
    }

    // join reduce1a, reduce1b, gemm2, fused final
    cudaStreamWaitEvent(0, g_side.e_r1a, 0);
    reduce1b_kernel<<<(PROWS * D0 + 255) / 256, 256>>>(seq_b0);

    {
        dim3 g2(D1 / 128, MR / 128, SPLIT2);
        mma_gemm_kernel<KT2, KT2 / SPLIT2, D1>
            <<<g2, 128, DSMEM>>>(a2, b1t, p2, 0);
    }
    final2_kernel<<<PROWS, 512>>>(seq_b1, seq_w2, seq_b2, out);
}

// round 17
// speedup vs baseline: 1.1102x; 1.0129x over previous
#include <cuda_runtime.h>
#include <cuda_fp16.h>
#include <cstdint>

// ---------------- problem constants ----------------
#define BB      10000
#define TED     512
#define GG      64
#define NN      2000
#define EE      64000
#define MDIM    15
#define NOISE_D 128
#define PAC     10
#define PROWS   1000          // B / PAC
#define PACDIM  6400          // (TED + NOISE) * PAC
#define D0      1024
#define D1      512

#define MR      1024
#define KINP    5120
#define KNOI    1280
#define KT1     PACDIM        // 6400
#define KT2     D0            // 1024
#define SPLITA  4
#define SPLITB  4
#define NSLICE  (SPLITA + SPLITB)   // 8
#define SPLIT2  4
#define GCN_SPL 8
#define EPC     (EE / GCN_SPL)

// ---------------- device scratch (static, allocation-free) ----------------
__device__ float d_deg [GG * NN];     // zero at load; gvec restores zero
__device__ float d_gout[GG * NN];     // zero at load; gvec restores zero
__device__ float d_gvecp[GG * 8 * NOISE_D];
__device__ __align__(16) __half d_a1 [(long)MR * KT1];
__device__ __align__(16) __half d_bt0[(long)D0 * KT1];
__device__ __align__(16) __half d_a2 [(long)MR * KT2];
__device__ __align__(16) __half d_b1t[(long)D1 * KT2];
__device__ __align__(16) float d_p1[(long)NSLICE * MR * D0];
__device__ __align__(16) float d_p2[(long)SPLIT2 * MR * D1];

// ---------------- side stream + events ----------------
struct SideStream {
    cudaStream_t s;
    cudaEvent_t e_fork, e_w0, e_r1a;
    SideStream() {
        cudaStreamCreateWithFlags(&s, cudaStreamNonBlocking);
        cudaEventCreateWithFlags(&e_fork, cudaEventDisableTiming);
        cudaEventCreateWithFlags(&e_w0, cudaEventDisableTiming);
        cudaEventCreateWithFlags(&e_r1a, cudaEventDisableTiming);
    }
};
static SideStream g_side;

// ---------------- PTX helpers ----------------
__device__ __forceinline__ uint32_t smem_u32(const void* p) {
    return (uint32_t)__cvta_generic_to_shared(p);
}
#define SWZ(off) ((off) ^ (((off) >> 3) & 0x70))

__device__ __forceinline__ void cp16(uint32_t dst, const void* src) {
    asm volatile("cp.async.cg.shared.global [%0], [%1], 16;" :: "r"(dst), "l"(src) : "memory");
}
#define CP_COMMIT() asm volatile("cp.async.commit_group;" ::: "memory")
#define CP_WAIT(n)  asm volatile("cp.async.wait_group %0;" :: "n"(n) : "memory")

__device__ __forceinline__ void ldsm_x4(uint32_t* d, uint32_t addr) {
    asm volatile("ldmatrix.sync.aligned.m8n8.x4.shared.b16 {%0,%1,%2,%3}, [%4];"
                 : "=r"(d[0]), "=r"(d[1]), "=r"(d[2]), "=r"(d[3]) : "r"(addr));
}
__device__ __forceinline__ void mma16816(float* c, const uint32_t* a, uint32_t b0, uint32_t b1) {
    asm volatile("mma.sync.aligned.m16n8k16.row.col.f32.f16.f16.f32 "
                 "{%0,%1,%2,%3}, {%4,%5,%6,%7}, {%8,%9}, {%0,%1,%2,%3};"
                 : "+f"(c[0]), "+f"(c[1]), "+f"(c[2]), "+f"(c[3])
                 : "r"(a[0]), "r"(a[1]), "r"(a[2]), "r"(a[3]), "r"(b0), "r"(b1));
}

// ---------------- GCN pass 1: partial degree ----------------
__global__ void __launch_bounds__(512)
gcn_deg_kernel(const int* __restrict__ ei) {
    __shared__ float s_deg[NN];
    int g = blockIdx.x >> 3, q = blockIdx.x & 7;
    int t = threadIdx.x;
    float init = (q == 0) ? 1.0f : 0.0f;
    for (int i = t; i < NN; i += 512) s_deg[i] = init;
    __syncthreads();
    const int4* dst4 = reinterpret_cast<const int4*>(
        ei + (long)g * 2 * EE + EE + q * EPC);
    for (int e = t; e < EPC / 4; e += 512) {
        int4 d = dst4[e];
        atomicAdd(&s_deg[d.x], 1.0f);
        atomicAdd(&s_deg[d.y], 1.0f);
        atomicAdd(&s_deg[d.z], 1.0f);
        atomicAdd(&s_deg[d.w], 1.0f);
    }
    __syncthreads();
    for (int i = t; i < NN; i += 512)
        atomicAdd(&d_deg[g * NN + i], s_deg[i]);
}

// ---------------- GCN pass 2: messages (dinv inline) ----------------
__global__ void __launch_bounds__(512)
gcn_msg_kernel(const int* __restrict__ ei, const float* __restrict__ gx,
               const float* __restrict__ gw, const float* __restrict__ gb) {
    __shared__ float s_xs [NN];
    __shared__ float s_di [NN];
    __shared__ float s_out[NN];
    int g = blockIdx.x >> 3, q = blockIdx.x & 7;
    int t = threadIdx.x;
    float w = gw[0], b = gb[0];
    bool lead = (q == 0);
    for (int i = t; i < NN; i += 512) {
        float dv = rsqrtf(d_deg[g * NN + i]);
        float xs = gx[g * NN + i] * w * dv;
        s_di[i] = dv;
        s_xs[i] = xs;
        s_out[i] = lead ? (xs * dv + b) : 0.0f;
    }
    __syncthreads();
    const int4* src4 = reinterpret_cast<const int4*>(ei + (long)g * 2 * EE + q * EPC);
    const int4* dst4 = reinterpret_cast<const int4*>(ei + (long)g * 2 * EE + EE + q * EPC);
    for (int e = t; e < EPC / 4; e += 512) {
        int4 s = src4[e];
        int4 d = dst4[e];
        atomicAdd(&s_out[d.x], s_xs[s.x] * s_di[d.x]);
        atomicAdd(&s_out[d.y], s_xs[s.y] * s_di[d.y]);
        atomicAdd(&s_out[d.z], s_xs[s.z] * s_di[d.z]);
        atomicAdd(&s_out[d.w], s_xs[s.w] * s_di[d.w]);
    }
    __syncthreads();
    for (int i = t; i < NN; i += 512)
        atomicAdd(&d_gout[g * NN + i], s_out[i]);
}

// ---------------- gvec partials + state restore ----------------
__global__ void gvec_kernel(const float* __restrict__ gme_w) {
    int g = blockIdx.x, c = blockIdx.y, j = threadIdx.x;
    __shared__ float sh[128];
    float a0 = 0.f, a1 = 0.f, a2 = 0.f, a3 = 0.f;
    int nbeg = c * 250, nend = nbeg + 250;
    for (int n0 = nbeg; n0 < nend; n0 += 128) {
        int n = n0 + j;
        float v = 0.0f;
        if (n < nend) {
            v = d_gout[g * NN + n];
            d_gout[g * NN + n] = 0.0f;
            d_deg [g * NN + n] = 0.0f;
        }
        sh[j] = v;
        __syncthreads();
        int lim = min(128, nend - n0);
        int i = 0;
        for (; i + 3 < lim; i += 4) {
            a0 = fmaf(sh[i],     gme_w[(long)(n0 + i)     * NOISE_D + j], a0);
            a1 = fmaf(sh[i + 1], gme_w[(long)(n0 + i + 1) * NOISE_D + j], a1);
            a2 = fmaf(sh[i + 2], gme_w[(long)(n0 + i + 2) * NOISE_D + j], a2);
            a3 = fmaf(sh[i + 3], gme_w[(long)(n0 + i + 3) * NOISE_D + j], a3);
        }
        for (; i < lim; ++i)
            a0 = fmaf(sh[i], gme_w[(long)(n0 + i) * NOISE_D + j], a0);
        __syncthreads();
    }
    d_gvecp[(g * 8 + c) * NOISE_D + j] = (a0 + a1) + (a2 + a3);
}

// ---------------- noise: 8 rows/block ----------------
__global__ void __launch_bounds__(128)
noise_kernel(const float* __restrict__ chain,
             const float* __restrict__ metadata,
             const int*   __restrict__ gids,
             const float* __restrict__ meta_w,
             const float* __restrict__ meta_b,
             const float* __restrict__ gme_w,
             const float* __restrict__ gme_b) {
    __shared__ float s_gw[32][NOISE_D];
    __shared__ float me[8][32];
    __shared__ int   sg[8];
    int b0 = blockIdx.x * 8, t = threadIdx.x;

    for (int i = t; i < 32 * NOISE_D; i += 128)
        s_gw[i >> 7][i & 127] = gme_w[(long)(NN + (i >> 7)) * NOISE_D + (i & 127)];
    if (t < 8) sg[t] = gids[b0 + t];

    #pragma unroll
    for (int rr = 0; rr < 2; ++rr) {
        int r = rr * 4 + (t >> 5);
        int c = t & 31;
        int b = b0 + r;
        float acc = meta_b[c];
        acc = fmaf(chain[b], meta_w[c], acc);
        #pragma unroll
        for (int i = 0; i < MDIM; ++i)
            acc = fmaf(metadata[b * MDIM + i], meta_w[(i + 1) * 32 + c], acc);
        me[r][c] = fmaxf(acc, 0.0f);
    }
    __syncthreads();

    float gb = gme_b[t];
    #pragma unroll
    for (int r = 0; r < 8; ++r) {
        int b = b0 + r, g = sg[r];
        float s = gb;
        #pragma unroll
        for (int c = 0; c < 8; ++c)
            s += d_gvecp[(g * 8 + c) * NOISE_D + t];
        #pragma unroll
        for (int i = 0; i < 32; ++i)
            s = fmaf(me[r][i], s_gw[i][t], s);
        int p = b / PAC, u = b - p * PAC;
        int k = KINP + u * NOISE_D + t;
        d_a1[(long)p * KT1 + k] = __float2half_rn(s);
    }
}

// ---------------- input_ -> fp16 A (input K region) ----------------
__global__ void copy_input_kernel(const float* __restrict__ input_) {
    int idx = blockIdx.x * blockDim.x + threadIdx.x;
    if (idx >= BB * (TED / 8)) return;
    int b = idx >> 6, q8 = (idx & 63) * 8;
    const float4* src = reinterpret_cast<const float4*>(input_ + (long)b * TED + q8);
    float4 v0 = src[0], v1 = src[1];
    __half2 h0 = __floats2half2_rn(v0.x, v0.y);
    __half2 h1 = __floats2half2_rn(v0.z, v0.w);
    __half2 h2 = __floats2half2_rn(v1.x, v1.y);
    __half2 h3 = __floats2half2_rn(v1.z, v1.w);
    int p = b / PAC, u = b - p * PAC;
    int k = u * TED + q8;
    __half2* dst = reinterpret_cast<__half2*>(&d_a1[(long)p * KT1 + k]);
    dst[0] = h0; dst[1] = h1; dst[2] = h2; dst[3] = h3;
}

// ---------------- fused weight transpose + fp16, half2 stores ----------------
// store phase: each thread writes __half2 (pairs of consecutive k). Pairs start
// even so they never straddle the 512/128 remap boundary within a u-segment.
#define W0_BLKS ((KT1 / 32) * (D0 / 32))
__global__ void __launch_bounds__(256)
convW_both_kernel(const float* __restrict__ w0, __half* __restrict__ bt0,
                  const float* __restrict__ w1, __half* __restrict__ b1t) {
    __shared__ float s[32][33];
    bool first = blockIdx.x < W0_BLKS;
    int bid = first ? blockIdx.x : blockIdx.x - W0_BLKS;
    const float* w = first ? w0 : w1;
    __half* out    = first ? bt0 : b1t;
    const int K = first ? KT1 : KT2;
    const int N = first ? D0 : D1;
    int kb = first ? (KT1 / 32) : (KT2 / 32);
    int k0 = (bid % kb) * 32, n0 = (bid / kb) * 32;

    int tx = threadIdx.x & 31, ty = threadIdx.x >> 5;
    #pragma unroll
    for (int r = 0; r < 4; ++r)
        s[ty + r * 8][tx] = w[(long)(k0 + ty + r * 8) * N + n0 + tx];
    __syncthreads();

    // store: 16 k-pairs (kx) x 16 n (ny), 2 n-iterations
    int kx = (threadIdx.x & 15) * 2;        // even k within tile
    int ny = threadIdx.x >> 4;              // 0..15
    #pragma unroll
    for (int r = 0; r < 2; ++r) {
        int n = n0 + ny + r * 16;
        int kk = k0 + kx;
        if (first) {
            int u = kk / 640, c = kk - u * 640;
            kk = (c < TED) ? (u * TED + c) : (KINP + u * NOISE_D + (c - TED));
        }
        __half2 v = __floats2half2_rn(s[kx][ny + r * 16], s[kx + 1][ny + r * 16]);
        *reinterpret_cast<__half2*>(&out[(long)n * K + kk]) = v;
    }
}

// ---------------- mma.sync fp16 GEMM: 128 thr, 4 warps 64x64, BK=64 ----------
template<int KTOT, int KSPLIT, int NTOT>
__global__ void __launch_bounds__(128, 2)
mma_gemm_kernel(const __half* __restrict__ A,
                const __half* __restrict__ Bt,
                float* __restrict__ Part, int kofs) {
    const int NITER = KSPLIT / 64;
    const int STG   = 32768;
    extern __shared__ __align__(1024) char sm[];
    uint32_t sb = smem_u32(sm);

    int tid = threadIdx.x;
    int lane = tid & 31;
    int wid  = tid >> 5;
    int wm   = wid & 1;
    int wn   = wid >> 1;
    int row0 = blockIdx.y * 128, col0 = blockIdx.x * 128;
    int kbase0 = kofs + blockIdx.z * KSPLIT;

    auto load_stage = [&](int stage, int kbase) {
        uint32_t aT = sb + stage * STG;
        uint32_t bT = aT + 16384;
        #pragma unroll
        for (int i = 0; i < 8; ++i) {
            int q = tid + 128 * i;
            int r = q >> 3, c = q & 7;
            cp16(aT + SWZ(r * 128 + c * 16),
                 A + (long)(row0 + r) * KTOT + kbase + c * 8);
        }
        #pragma unroll
        for (int i = 0; i < 8; ++i) {
            int q = tid + 128 * i;
            int r = q >> 3, c = q & 7;
            cp16(bT + SWZ(r * 128 + c * 16),
                 Bt + (long)(col0 + r) * KTOT + kbase + c * 8);
        }
    };

    float acc[4][8][4];
    #pragma unroll
    for (int mf = 0; mf < 4; ++mf)
        #pragma unroll
        for (int nf = 0; nf < 8; ++nf)
            #pragma unroll
            for (int j = 0; j < 4; ++j) acc[mf][nf][j] = 0.0f;

    load_stage(0, kbase0); CP_COMMIT();
    load_stage(1, kbase0 + 64); CP_COMMIT();

    int a_row = wm * 64 + (lane & 15);
    int a_kb  = (lane >> 4) << 4;
    int b_row = wn * 64 + (lane & 7) + ((lane >> 4) & 1) * 8;
    int b_kb  = ((lane >> 3) & 1) << 4;

    for (int it = 0; it < NITER; ++it) {
        CP_WAIT(1);
        __syncthreads();
        if (it + 2 < NITER) load_stage((it + 2) % 3, kbase0 + (it + 2) * 64);
        CP_COMMIT();

        uint32_t aT = sb + (it % 3) * STG;
        uint32_t bT = aT + 16384;

        #pragma unroll
        for (int kk = 0; kk < 4; ++kk) {
            uint32_t a[4][4];
            #pragma unroll
            for (int mf = 0; mf < 4; ++mf)
                ldsm_x4(a[mf], aT + SWZ((a_row + mf * 16) * 128 + kk * 32 + a_kb));
            uint32_t b[4][4];
            #pragma unroll
            for (int nfp = 0; nfp < 4; ++nfp)
                ldsm_x4(b[nfp], bT + SWZ((b_row + nfp * 16) * 128 + kk * 32 + b_kb));
            #pragma unroll
            for (int mf = 0; mf < 4; ++mf)
                #pragma unroll
                for (int nfp = 0; nfp < 4; ++nfp) {
                    mma16816(acc[mf][2 * nfp],     a[mf], b[nfp][0], b[nfp][1]);
                    mma16816(acc[mf][2 * nfp + 1], a[mf], b[nfp][2], b[nfp][3]);
                }
        }
    }

    float* P = Part + (long)blockIdx.z * MR * NTOT;
    #pragma unroll
    for (int mf = 0; mf < 4; ++mf) {
        int gr = row0 + wm * 64 + mf * 16 + (lane >> 2);
        #pragma unroll
        for (int nf = 0; nf < 8; ++nf) {
            int gc = col0 + wn * 64 + nf * 8 + (lane & 3) * 2;
            *reinterpret_cast<float2*>(&P[(long)gr * NTOT + gc]) =
                make_float2(acc[mf][nf][0], acc[mf][nf][1]);
            *reinterpret_cast<float2*>(&P[(long)(gr + 8) * NTOT + gc]) =
                make_float2(acc[mf][nf][2], acc[mf][nf][3]);
        }
    }
}

// reduce1a: pre-sum gemmA slices 0..3 into slice 0 (runs concurrent w/ gemmB)
__global__ void reduce1a_kernel() {
    long i = (long)blockIdx.x * blockDim.x + threadIdx.x;
    if (i >= (long)PROWS * D0) return;
    int m = (int)(i >> 10), n = (int)(i & 1023);
    long o = (long)m * D0 + n;
    float v = d_p1[o];
    #pragma unroll
    for (int s = 1; s < SPLITA; ++s)
        v += d_p1[(long)s * MR * D0 + o];
    d_p1[o] = v;
}

// reduce1b: slice0 + gemmB slices + bias + lrelu -> fp16 A2
__global__ void reduce1b_kernel(const float* __restrict__ bias) {
    long i = (long)blockIdx.x * blockDim.x + threadIdx.x;
    if (i >= (long)PROWS * D0) return;
    int m = (int)(i >> 10), n = (int)(i & 1023);
    long o = (long)m * D0 + n;
    float v = d_p1[o];
    #pragma unroll
    for (int s = SPLITA; s < NSLICE; ++s)
        v += d_p1[(long)s * MR * D0 + o];
    v += bias[n];
    v = (v >= 0.f) ? v : 0.2f * v;
    d_a2[(long)m * KT2 + n] = __float2half_rn(v);
}

// fused: reduce gemm2 slices + bias + lrelu + dot(w2) + b2 -> out
__global__ void __launch_bounds__(512)
final2_kernel(const float* __restrict__ b1,
              const float* __restrict__ w2,
              const float* __restrict__ b2,
              float* __restrict__ out) {
    int m = blockIdx.x, t = threadIdx.x;
    float v = 0.0f;
    #pragma unroll
    for (int s = 0; s < SPLIT2; ++s)
        v += d_p2[(long)s * MR * D1 + (long)m * D1 + t];
    v += b1[t];
    v = (v >= 0.f) ? v : 0.2f * v;
    float s = v * w2[t];
    #pragma unroll
    for (int off = 16; off > 0; off >>= 1)
        s += __shfl_down_sync(0xffffffff, s, off);
    __shared__ float ws[16];
    if ((t & 31) == 0) ws[t >> 5] = s;
    __syncthreads();
    if (t < 32) {
        float r = (t < 16) ? ws[t] : 0.0f;
        #pragma unroll
        for (int off = 8; off > 0; off >>= 1)
            r += __shfl_down_sync(0xffffffff, r, off);
        if (t == 0) out[m] = r + b2[0];
    }
}

// ---------------- launch ----------------
extern "C" void kernel_launch(void* const* d_in, const int* in_sizes, int n_in,
                              void* d_out, int out_size) {
    const float* input_   = (const float*)d_in[0];
    const float* graphs_x = (const float*)d_in[1];
    const int*   edge_idx = (const int*)  d_in[2];
    const int*   graph_id = (const int*)  d_in[3];
    const float* chain    = (const float*)d_in[4];
    const float* metadata = (const float*)d_in[5];
    const float* gcn_w    = (const float*)d_in[6];
    const float* gcn_b    = (const float*)d_in[7];
    const float* meta_w   = (const float*)d_in[8];
    const float* meta_b   = (const float*)d_in[9];
    const float* gme_w    = (const float*)d_in[10];
    const float* gme_b    = (const float*)d_in[11];
    const float* seq_w0   = (const float*)d_in[12];
    const float* seq_b0   = (const float*)d_in[13];
    const float* seq_w1   = (const float*)d_in[14];
    const float* seq_b1   = (const float*)d_in[15];
    const float* seq_w2   = (const float*)d_in[16];
    const float* seq_b2   = (const float*)d_in[17];
    float* out = (float*)d_out;

    const int DSMEM = 3 * 32768;   // 96 KB
    cudaFuncSetAttribute((const void*)mma_gemm_kernel<KT1, KINP / SPLITA, D0>,
                         cudaFuncAttributeMaxDynamicSharedMemorySize, DSMEM);
    cudaFuncSetAttribute((const void*)mma_gemm_kernel<KT1, KNOI / SPLITB, D0>,
                         cudaFuncAttributeMaxDynamicSharedMemorySize, DSMEM);
    cudaFuncSetAttribute((const void*)mma_gemm_kernel<KT2, KT2 / SPLIT2, D1>,
                         cudaFuncAttributeMaxDynamicSharedMemorySize, DSMEM);

    __half *a1, *bt0, *a2, *b1t;
    float *p1, *p2;
    cudaGetSymbolAddress((void**)&a1,  d_a1);
    cudaGetSymbolAddress((void**)&bt0, d_bt0);
    cudaGetSymbolAddress((void**)&a2,  d_a2);
    cudaGetSymbolAddress((void**)&b1t, d_b1t);
    cudaGetSymbolAddress((void**)&p1,  d_p1);
    cudaGetSymbolAddress((void**)&p2,  d_p2);

    // ---- fork ----
    cudaEventRecord(g_side.e_fork, 0);
    cudaStreamWaitEvent(g_side.s, g_side.e_fork, 0);

    // side stream: convW(both) -> copy_input -> gemmA -> reduce1a (slices 0..3)
    convW_both_kernel<<<W0_BLKS + (KT2 / 32) * (D1 / 32), 256, 0, g_side.s>>>(
        seq_w0, bt0, seq_w1, b1t);
    cudaEventRecord(g_side.e_w0, g_side.s);
    copy_input_kernel<<<(BB * (TED / 8) + 255) / 256, 256, 0, g_side.s>>>(input_);
    {
        dim3 gA(D0 / 128, MR / 128, SPLITA);
        mma_gemm_kernel<KT1, KINP / SPLITA, D0>
            <<<gA, 128, DSMEM, g_side.s>>>(a1, bt0, p1, 0);
    }
    reduce1a_kernel<<<(PROWS * D0 + 255) / 256, 256, 0, g_side.s>>>();
    cudaEventRecord(g_side.e_r1a, g_side.s);

    // main stream: GCN (deg -> msg) -> gvec (restores state) -> noise
    gcn_deg_kernel<<<GG * GCN_SPL, 512>>>(edge_idx);
    gcn_msg_kernel<<<GG * GCN_SPL, 512>>>(edge_idx, graphs_x, gcn_w, gcn_b);
    gvec_kernel<<<dim3(GG, 8), 128>>>(gme_w);
    noise_kernel<<<BB / 8, 128>>>(chain, metadata, graph_id, meta_w, meta_b, gme_w, gme_b);

    // gemmB (noise-K region): slices 4..7 (concurrent with reduce1a on side)
    cudaStreamWaitEvent(0, g_side.e_w0, 0);
    {
        dim3 gB(D0 / 128, MR / 128, SPLITB);
        mma_gemm_kernel<KT1, KNOI / SPLITB, D0>
            <<<gB, 128, DSMEM>>>(a1, bt0, p1 + (long)SPLITA * MR * D0, KINP);
    }

    // join reduce1a, reduce1b, gemm2, fused final
    cudaStreamWaitEvent(0, g_side.e_r1a, 0);
    reduce1b_kernel<<<(PROWS * D0 + 255) / 256, 256>>>(seq_b0);

    {
        dim3 g2(D1 / 128, MR / 128, SPLIT2);
        mma_gemm_kernel<KT2, KT2 / SPLIT2, D1>
            <<<g2, 128, DSMEM>>>(a2, b1t, p2, 0);
    }
    final2_kernel<<<PROWS, 512>>>(seq_b1, seq_w2, seq_b2, out);
}